// round 3
// baseline (speedup 1.0000x reference)
#include <cuda_runtime.h>

#define NN 50000
#define NE 800000
#define HD 128

// ---------------- device scratch (no allocations allowed) ----------------
__device__ float g_y[(size_t)NN * HD];   // scaled xw (GEMM output)
__device__ float g_x[(size_t)NN * HD];   // running x
__device__ float g_h[(size_t)NN * HD];   // block intermediate h
__device__ float g_norm[NN];
__device__ int   g_rowptr[NN + 1];
__device__ int   g_cnt[NN];
__device__ int   g_off[NN];
__device__ int   g_col[NE];

__device__ __forceinline__ float lk(float v) { return v >= 0.f ? v : 0.01f * v; }

// ---------------- CSR build ----------------
__global__ void zero_cnt_kernel() {
    int i = blockIdx.x * blockDim.x + threadIdx.x;
    if (i < NN) g_cnt[i] = 0;
}

__global__ void count_kernel(const int* __restrict__ dst) {
    int e = blockIdx.x * blockDim.x + threadIdx.x;
    if (e < NE) atomicAdd(&g_cnt[dst[e]], 1);
}

// single block, 1024 threads: exclusive scan of g_cnt -> g_rowptr (+ g_off copy),
// and norm[i] = rsqrt(1 + deg[i])
__global__ void scan_norm_kernel() {
    __shared__ int wsum[32];
    __shared__ int carry;
    int tid = threadIdx.x, lane = tid & 31, wid = tid >> 5;
    if (tid == 0) carry = 0;
    __syncthreads();
    for (int base = 0; base < NN; base += 1024) {
        int i = base + tid;
        int v = (i < NN) ? g_cnt[i] : 0;
        int x = v;
#pragma unroll
        for (int d = 1; d < 32; d <<= 1) {
            int t = __shfl_up_sync(0xffffffffu, x, d);
            if (lane >= d) x += t;
        }
        if (lane == 31) wsum[wid] = x;
        __syncthreads();
        if (wid == 0) {
            int s = wsum[lane];
#pragma unroll
            for (int d = 1; d < 32; d <<= 1) {
                int t = __shfl_up_sync(0xffffffffu, s, d);
                if (lane >= d) s += t;
            }
            wsum[lane] = s;
        }
        __syncthreads();
        int off = carry + (wid ? wsum[wid - 1] : 0);
        int incl = off + x;
        if (i < NN) {
            int excl = incl - v;
            g_rowptr[i] = excl;
            g_off[i]    = excl;
            g_norm[i]   = rsqrtf(1.0f + (float)v);
        }
        __syncthreads();
        if (tid == 1023) carry = incl;
        __syncthreads();
    }
    if (threadIdx.x == 0) g_rowptr[NN] = carry;
}

__global__ void fill_kernel(const int* __restrict__ src, const int* __restrict__ dst) {
    int e = blockIdx.x * blockDim.x + threadIdx.x;
    if (e < NE) {
        int d = dst[e];
        int p = atomicAdd(&g_off[d], 1);
        g_col[p] = src[e];
    }
}

// ---------------- GEMM: Y[m,:] = (A[m,:] @ W) * norm[m]   (K = 128) ----------------
// BM=128, BK=32, 256 threads (8 warps). warp w owns rows w*16..w*16+15,
// lane owns TN contiguous output cols (TN = BN/32). A-reads broadcast, B-reads vec.
template <int BN>
__global__ __launch_bounds__(256) void gemm_scale_kernel(const float* __restrict__ A,
                                                         const float* __restrict__ W,
                                                         float* __restrict__ Y) {
    constexpr int BM = 128, BK = 32, K = 128;
    constexpr int TN = BN / 32;  // 4 (BN=128) or 2 (BN=64)
    __shared__ float As[BM][BK];
    __shared__ float Bs[BK][BN];
    int tid = threadIdx.x, lane = tid & 31, w = tid >> 5;
    int m0 = blockIdx.x * BM;
    float acc[16][TN];
#pragma unroll
    for (int i = 0; i < 16; i++)
#pragma unroll
        for (int j = 0; j < TN; j++) acc[i][j] = 0.f;

    for (int k0 = 0; k0 < K; k0 += BK) {
        // A tile: 128x32 = 1024 float4, 4 per thread, coalesced
#pragma unroll
        for (int l = 0; l < 4; l++) {
            int f = tid + l * 256;
            int r = f >> 3, c = f & 7;
            float4 v = make_float4(0.f, 0.f, 0.f, 0.f);
            if (m0 + r < NN) v = *(const float4*)(A + (size_t)(m0 + r) * K + k0 + c * 4);
            *(float4*)&As[r][c * 4] = v;
        }
        // B tile: BKxBN
#pragma unroll
        for (int l = 0; l < (BK * BN) / (4 * 256); l++) {
            int f = tid + l * 256;
            int r = f / (BN / 4), c = f % (BN / 4);
            *(float4*)&Bs[r][c * 4] = *(const float4*)(W + (size_t)(k0 + r) * BN + c * 4);
        }
        __syncthreads();
#pragma unroll
        for (int k = 0; k < BK; k += 4) {
            float bk[4][TN];
#pragma unroll
            for (int kk = 0; kk < 4; kk++) {
                if constexpr (TN == 4) {
                    float4 t = *(const float4*)&Bs[k + kk][lane * 4];
                    bk[kk][0] = t.x; bk[kk][1] = t.y; bk[kk][2] = t.z; bk[kk][3] = t.w;
                } else {
                    float2 t = *(const float2*)&Bs[k + kk][lane * 2];
                    bk[kk][0] = t.x; bk[kk][1] = t.y;
                }
            }
#pragma unroll
            for (int i = 0; i < 16; i++) {
                float4 av = *(const float4*)&As[w * 16 + i][k];
                float aa[4] = {av.x, av.y, av.z, av.w};
#pragma unroll
                for (int kk = 0; kk < 4; kk++)
#pragma unroll
                    for (int j = 0; j < TN; j++) acc[i][j] += aa[kk] * bk[kk][j];
            }
        }
        __syncthreads();
    }
#pragma unroll
    for (int i = 0; i < 16; i++) {
        int m = m0 + w * 16 + i;
        if (m < NN) {
            float nm = g_norm[m];
            if constexpr (TN == 4) {
                float4 o = make_float4(acc[i][0] * nm, acc[i][1] * nm, acc[i][2] * nm, acc[i][3] * nm);
                *(float4*)(Y + (size_t)m * BN + lane * 4) = o;
            } else {
                float2 o = make_float2(acc[i][0] * nm, acc[i][1] * nm);
                *(float2*)(Y + (size_t)m * BN + lane * 2) = o;
            }
        }
    }
}

// ---------------- Aggregation: one warp per node ----------------
// out[n] = f( norm[n] * (y[n] + sum_{e: dst=n} y[src_e]) + bias )
// MODE 0: out = leaky(o)
// MODE 1: out = (out_old + leaky(o)) * 0.5   (residual, in-place on outp)
// MODE 2: out = o (no activation; final conv, D=64)
template <int D, int MODE>
__global__ __launch_bounds__(256) void agg_kernel(const float* __restrict__ Y,
                                                  const float* __restrict__ bias,
                                                  float* __restrict__ outp) {
    int gw = (blockIdx.x * 256 + threadIdx.x) >> 5;
    if (gw >= NN) return;
    int lane = threadIdx.x & 31;
    int beg = g_rowptr[gw], end = g_rowptr[gw + 1];
    float nm = g_norm[gw];
    if constexpr (D == 128) {
        const float4* Y4 = (const float4*)Y;
        float4 acc = Y4[(size_t)gw * 32 + lane];  // self-loop term
        int sn = (beg < end) ? g_col[beg] : 0;
        for (int e = beg; e < end; e++) {
            int s = sn;
            if (e + 1 < end) sn = g_col[e + 1];
            float4 v = Y4[(size_t)s * 32 + lane];
            acc.x += v.x; acc.y += v.y; acc.z += v.z; acc.w += v.w;
        }
        float4 b = ((const float4*)bias)[lane];
        float4 o = make_float4(acc.x * nm + b.x, acc.y * nm + b.y,
                               acc.z * nm + b.z, acc.w * nm + b.w);
        float4* O4 = (float4*)outp;
        size_t idx = (size_t)gw * 32 + lane;
        if constexpr (MODE == 0) {
            O4[idx] = make_float4(lk(o.x), lk(o.y), lk(o.z), lk(o.w));
        } else if constexpr (MODE == 1) {
            float4 r = O4[idx];
            O4[idx] = make_float4((r.x + lk(o.x)) * 0.5f, (r.y + lk(o.y)) * 0.5f,
                                  (r.z + lk(o.z)) * 0.5f, (r.w + lk(o.w)) * 0.5f);
        } else {
            O4[idx] = o;
        }
    } else {  // D == 64
        const float2* Y2 = (const float2*)Y;
        float2 acc = Y2[(size_t)gw * 32 + lane];
        int sn = (beg < end) ? g_col[beg] : 0;
        for (int e = beg; e < end; e++) {
            int s = sn;
            if (e + 1 < end) sn = g_col[e + 1];
            float2 v = Y2[(size_t)s * 32 + lane];
            acc.x += v.x; acc.y += v.y;
        }
        float2 b = ((const float2*)bias)[lane];
        float2 o = make_float2(acc.x * nm + b.x, acc.y * nm + b.y);
        float2* O2 = (float2*)outp;
        size_t idx = (size_t)gw * 32 + lane;
        if constexpr (MODE == 0) {
            O2[idx] = make_float2(lk(o.x), lk(o.y));
        } else if constexpr (MODE == 1) {
            float2 r = O2[idx];
            O2[idx] = make_float2((r.x + lk(o.x)) * 0.5f, (r.y + lk(o.y)) * 0.5f);
        } else {
            O2[idx] = o;
        }
    }
}

// ---------------- launch ----------------
extern "C" void kernel_launch(void* const* d_in, const int* in_sizes, int n_in,
                              void* d_out, int out_size) {
    const float* inputs = (const float*)d_in[0];
    const int*   edges  = (const int*)d_in[1];
    const float* w_in   = (const float*)d_in[2];
    const float* b_in   = (const float*)d_in[3];
    const float* w1     = (const float*)d_in[4];
    const float* b1     = (const float*)d_in[5];
    const float* w2     = (const float*)d_in[6];
    const float* b2     = (const float*)d_in[7];
    const float* w_out  = (const float*)d_in[8];
    const float* b_out  = (const float*)d_in[9];
    float* out = (float*)d_out;

    const int* src = edges;
    const int* dst = edges + NE;

    void *pyv, *pxv, *phv;
    cudaGetSymbolAddress(&pyv, g_y);
    cudaGetSymbolAddress(&pxv, g_x);
    cudaGetSymbolAddress(&phv, g_h);
    float* yv = (float*)pyv;
    float* xv = (float*)pxv;
    float* hv = (float*)phv;

    const int GN  = (NN + 255) / 256;
    const int GE  = (NE + 255) / 256;
    const int GG  = (NN + 127) / 128;         // gemm blocks
    const int GA  = (NN * 32 + 255) / 256;    // agg blocks (warp/node)

    // CSR build (per launch; edges are an input)
    zero_cnt_kernel<<<GN, 256>>>();
    count_kernel<<<GE, 256>>>(dst);
    scan_norm_kernel<<<1, 1024>>>();
    fill_kernel<<<GE, 256>>>(src, dst);

    // input conv
    gemm_scale_kernel<128><<<GG, 256>>>(inputs, w_in, yv);
    agg_kernel<128, 0><<<GA, 256>>>(yv, b_in, xv);

    // 6 residual blocks
    for (int i = 0; i < 6; i++) {
        gemm_scale_kernel<128><<<GG, 256>>>(xv, w1 + (size_t)i * HD * HD, yv);
        agg_kernel<128, 0><<<GA, 256>>>(yv, b1 + (size_t)i * HD, hv);
        gemm_scale_kernel<128><<<GG, 256>>>(hv, w2 + (size_t)i * HD * HD, yv);
        agg_kernel<128, 1><<<GA, 256>>>(yv, b2 + (size_t)i * HD, xv);
    }

    // output conv (no activation), writes first N*64 floats of d_out
    gemm_scale_kernel<64><<<GG, 256>>>(xv, w_out, yv);
    agg_kernel<64, 2><<<GA, 256>>>(yv, b_out, out);

    // second output: x (N*128) after the blocks
    cudaMemcpyAsync(out + (size_t)NN * 64, xv, (size_t)NN * HD * sizeof(float),
                    cudaMemcpyDeviceToDevice);
}

// round 4
// speedup vs baseline: 1.4703x; 1.4703x over previous
#include <cuda_runtime.h>
#include <cuda_fp16.h>
#include <cuda_bf16.h>

#define NN 50000
#define NE 800000
#define HD 128
#define NMAT 14

// ---------------- device scratch (no allocations allowed) ----------------
__device__ __half  g_yh[(size_t)NN * HD];   // fp16 messages (GEMM output, norm-scaled)
__device__ float   g_x[(size_t)NN * HD];    // running x (fp32)
__device__ float   g_h[(size_t)NN * HD];    // block intermediate h
__device__ float   g_norm[NN];
__device__ int     g_rowptr[NN + 1];
__device__ int     g_cnt[NN];
__device__ int     g_off[NN];
__device__ int     g_col[NE];
__device__ __nv_bfloat16 g_wh[(size_t)NMAT * HD * HD];  // weights, n-major, hi part
__device__ __nv_bfloat16 g_wl[(size_t)NMAT * HD * HD];  // lo part

__device__ __forceinline__ float lk(float v) { return v >= 0.f ? v : 0.01f * v; }

__device__ __forceinline__ float2 u2f2(unsigned u) {
    __half2 h = *reinterpret_cast<__half2*>(&u);
    return __half22float2(h);
}

// ---------------- CSR build ----------------
__global__ void zero_cnt_kernel() {
    int i = blockIdx.x * blockDim.x + threadIdx.x;
    if (i < NN) g_cnt[i] = 0;
}

__global__ void count_kernel(const int* __restrict__ dst) {
    int e = blockIdx.x * blockDim.x + threadIdx.x;
    if (e < NE) atomicAdd(&g_cnt[dst[e]], 1);
}

__global__ void scan_norm_kernel() {
    __shared__ int wsum[32];
    __shared__ int carry;
    int tid = threadIdx.x, lane = tid & 31, wid = tid >> 5;
    if (tid == 0) carry = 0;
    __syncthreads();
    for (int base = 0; base < NN; base += 1024) {
        int i = base + tid;
        int v = (i < NN) ? g_cnt[i] : 0;
        int x = v;
#pragma unroll
        for (int d = 1; d < 32; d <<= 1) {
            int t = __shfl_up_sync(0xffffffffu, x, d);
            if (lane >= d) x += t;
        }
        if (lane == 31) wsum[wid] = x;
        __syncthreads();
        if (wid == 0) {
            int s = wsum[lane];
#pragma unroll
            for (int d = 1; d < 32; d <<= 1) {
                int t = __shfl_up_sync(0xffffffffu, s, d);
                if (lane >= d) s += t;
            }
            wsum[lane] = s;
        }
        __syncthreads();
        int off = carry + (wid ? wsum[wid - 1] : 0);
        int incl = off + x;
        if (i < NN) {
            int excl = incl - v;
            g_rowptr[i] = excl;
            g_off[i]    = excl;
            g_norm[i]   = rsqrtf(1.0f + (float)v);
        }
        __syncthreads();
        if (tid == 1023) carry = incl;
        __syncthreads();
    }
    if (threadIdx.x == 0) g_rowptr[NN] = carry;
}

__global__ void fill_kernel(const int* __restrict__ src, const int* __restrict__ dst) {
    int e = blockIdx.x * blockDim.x + threadIdx.x;
    if (e < NE) {
        int d = dst[e];
        int p = atomicAdd(&g_off[d], 1);
        g_col[p] = src[e];
    }
}

// ---------------- weight prep: transpose to n-major, split fp32 -> bf16 hi/lo ----
__global__ void prep_w_kernel(const float* __restrict__ w_in, const float* __restrict__ w1,
                              const float* __restrict__ w2, const float* __restrict__ w_out) {
    int idx = blockIdx.x * blockDim.x + threadIdx.x;
    if (idx >= NMAT * HD * HD) return;
    int mat = idx >> 14;         // / 16384
    int rem = idx & 16383;
    int n = rem >> 7, k = rem & 127;
    float v;
    if (mat == 0)       v = w_in[k * HD + n];
    else if (mat <= 6)  v = w1[(size_t)(mat - 1) * HD * HD + k * HD + n];
    else if (mat <= 12) v = w2[(size_t)(mat - 7) * HD * HD + k * HD + n];
    else                v = (n < 64) ? w_out[k * 64 + n] : 0.f;
    __nv_bfloat16 hi = __float2bfloat16(v);
    __nv_bfloat16 lo = __float2bfloat16(v - __bfloat162float(hi));
    g_wh[idx] = hi;
    g_wl[idx] = lo;
}

// ---------------- bf16x2 split tensor-core GEMM ----------------
// Yh[m,:] = half( (A[m,:] @ W) * norm[m] ),  K = 128.
// BM=128, BK=32, 256 threads = 8 warps (2 m x 4 n). warp tile 64 x (BN/4).
// smem: halves, row stride 40 (conflict-free fragment LDS: bank=(20g+t)%32).
__device__ __forceinline__ void mma_bf16(float* c, unsigned a0, unsigned a1, unsigned a2,
                                         unsigned a3, unsigned b0, unsigned b1) {
    asm volatile(
        "mma.sync.aligned.m16n8k16.row.col.f32.bf16.bf16.f32 "
        "{%0,%1,%2,%3}, {%4,%5,%6,%7}, {%8,%9}, {%0,%1,%2,%3};"
        : "+f"(c[0]), "+f"(c[1]), "+f"(c[2]), "+f"(c[3])
        : "r"(a0), "r"(a1), "r"(a2), "r"(a3), "r"(b0), "r"(b1));
}

template <int BN>
__global__ __launch_bounds__(256) void gemm_tc_kernel(const float* __restrict__ A,
                                                      const __nv_bfloat16* __restrict__ Wh,
                                                      const __nv_bfloat16* __restrict__ Wl,
                                                      __half* __restrict__ Yh) {
    constexpr int BM = 128, BK = 32, K = 128;
    constexpr int WN = BN / 4;   // warp n-extent: 32 or 16
    constexpr int NT = WN / 8;   // n-tiles per warp: 4 or 2
    constexpr int SA = 40;       // smem stride in halves
    __shared__ __nv_bfloat16 sAh[BM * SA], sAl[BM * SA];
    __shared__ __nv_bfloat16 sBh[BN * SA], sBl[BN * SA];

    const int tid = threadIdx.x, lane = tid & 31, wid = tid >> 5;
    const int g = lane >> 2, t = lane & 3;
    const int wm = (wid & 1) * 64, wn = (wid >> 1) * WN;
    const int m0 = blockIdx.x * BM;

    float acc[4][NT][4];
#pragma unroll
    for (int i = 0; i < 4; i++)
#pragma unroll
        for (int j = 0; j < NT; j++)
#pragma unroll
            for (int q = 0; q < 4; q++) acc[i][j][q] = 0.f;

    // staged registers (prefetch)
    float4 va[4];
    uint4 vbh[2], vbl[2];

    auto loadA = [&](int k0) {
#pragma unroll
        for (int l = 0; l < 4; l++) {
            int idx = tid + l * 256, r = idx >> 3, c = idx & 7;
            va[l] = make_float4(0.f, 0.f, 0.f, 0.f);
            if (m0 + r < NN) va[l] = *(const float4*)(A + (size_t)(m0 + r) * K + k0 + c * 4);
        }
    };
    auto loadB = [&](int k0) {
        if constexpr (BN == 128) {
            int n = tid >> 1, kh = (tid & 1) * 16;
            vbh[0] = *(const uint4*)&Wh[(size_t)n * K + k0 + kh];
            vbh[1] = *(const uint4*)&Wh[(size_t)n * K + k0 + kh + 8];
            vbl[0] = *(const uint4*)&Wl[(size_t)n * K + k0 + kh];
            vbl[1] = *(const uint4*)&Wl[(size_t)n * K + k0 + kh + 8];
        } else {
            int n = tid >> 2, kh = (tid & 3) * 8;
            vbh[0] = *(const uint4*)&Wh[(size_t)n * K + k0 + kh];
            vbl[0] = *(const uint4*)&Wl[(size_t)n * K + k0 + kh];
        }
    };
    auto storeTiles = [&]() {
#pragma unroll
        for (int l = 0; l < 4; l++) {
            int idx = tid + l * 256, r = idx >> 3, c = idx & 7;
            float4 v = va[l];
            __nv_bfloat16 h0 = __float2bfloat16(v.x), h1 = __float2bfloat16(v.y);
            __nv_bfloat16 h2 = __float2bfloat16(v.z), h3 = __float2bfloat16(v.w);
            __nv_bfloat162 p01, p23, q01, q23;
            p01.x = h0; p01.y = h1; p23.x = h2; p23.y = h3;
            q01.x = __float2bfloat16(v.x - __bfloat162float(h0));
            q01.y = __float2bfloat16(v.y - __bfloat162float(h1));
            q23.x = __float2bfloat16(v.z - __bfloat162float(h2));
            q23.y = __float2bfloat16(v.w - __bfloat162float(h3));
            *(__nv_bfloat162*)&sAh[r * SA + c * 4]     = p01;
            *(__nv_bfloat162*)&sAh[r * SA + c * 4 + 2] = p23;
            *(__nv_bfloat162*)&sAl[r * SA + c * 4]     = q01;
            *(__nv_bfloat162*)&sAl[r * SA + c * 4 + 2] = q23;
        }
        if constexpr (BN == 128) {
            int n = tid >> 1, kh = (tid & 1) * 16;
            *(uint4*)&sBh[n * SA + kh]     = vbh[0];
            *(uint4*)&sBh[n * SA + kh + 8] = vbh[1];
            *(uint4*)&sBl[n * SA + kh]     = vbl[0];
            *(uint4*)&sBl[n * SA + kh + 8] = vbl[1];
        } else {
            int n = tid >> 2, kh = (tid & 3) * 8;
            *(uint4*)&sBh[n * SA + kh] = vbh[0];
            *(uint4*)&sBl[n * SA + kh] = vbl[0];
        }
    };

    loadA(0);
    loadB(0);
    for (int k0 = 0; k0 < K; k0 += BK) {
        storeTiles();
        __syncthreads();
        if (k0 + BK < K) { loadA(k0 + BK); loadB(k0 + BK); }
#pragma unroll
        for (int kk = 0; kk < BK; kk += 16) {
            unsigned bh[NT][2], bl[NT][2];
#pragma unroll
            for (int nt = 0; nt < NT; nt++) {
                int n = wn + nt * 8 + g;
                bh[nt][0] = *(const unsigned*)&sBh[n * SA + kk + 2 * t];
                bh[nt][1] = *(const unsigned*)&sBh[n * SA + kk + 2 * t + 8];
                bl[nt][0] = *(const unsigned*)&sBl[n * SA + kk + 2 * t];
                bl[nt][1] = *(const unsigned*)&sBl[n * SA + kk + 2 * t + 8];
            }
#pragma unroll
            for (int mt = 0; mt < 4; mt++) {
                int m = wm + mt * 16 + g;
                unsigned ah0 = *(const unsigned*)&sAh[m * SA + kk + 2 * t];
                unsigned ah1 = *(const unsigned*)&sAh[(m + 8) * SA + kk + 2 * t];
                unsigned ah2 = *(const unsigned*)&sAh[m * SA + kk + 2 * t + 8];
                unsigned ah3 = *(const unsigned*)&sAh[(m + 8) * SA + kk + 2 * t + 8];
                unsigned al0 = *(const unsigned*)&sAl[m * SA + kk + 2 * t];
                unsigned al1 = *(const unsigned*)&sAl[(m + 8) * SA + kk + 2 * t];
                unsigned al2 = *(const unsigned*)&sAl[m * SA + kk + 2 * t + 8];
                unsigned al3 = *(const unsigned*)&sAl[(m + 8) * SA + kk + 2 * t + 8];
#pragma unroll
                for (int nt = 0; nt < NT; nt++) {
                    mma_bf16(acc[mt][nt], ah0, ah1, ah2, ah3, bh[nt][0], bh[nt][1]);
                    mma_bf16(acc[mt][nt], ah0, ah1, ah2, ah3, bl[nt][0], bl[nt][1]);
                    mma_bf16(acc[mt][nt], al0, al1, al2, al3, bh[nt][0], bh[nt][1]);
                }
            }
        }
        __syncthreads();
    }

    // epilogue: scale by norm, convert to half
#pragma unroll
    for (int mt = 0; mt < 4; mt++) {
        int r0 = m0 + wm + mt * 16 + g, r1 = r0 + 8;
        float n0 = (r0 < NN) ? g_norm[r0] : 0.f;
        float n1 = (r1 < NN) ? g_norm[r1] : 0.f;
#pragma unroll
        for (int nt = 0; nt < NT; nt++) {
            int col = wn + nt * 8 + 2 * t;
            if (r0 < NN) {
                __half2 h = __floats2half2_rn(acc[mt][nt][0] * n0, acc[mt][nt][1] * n0);
                *(__half2*)(Yh + (size_t)r0 * BN + col) = h;
            }
            if (r1 < NN) {
                __half2 h = __floats2half2_rn(acc[mt][nt][2] * n1, acc[mt][nt][3] * n1);
                *(__half2*)(Yh + (size_t)r1 * BN + col) = h;
            }
        }
    }
}

// ---------------- Aggregation: one warp per node, fp16 gather, fp32 accum --------
// out[n] = f( norm[n] * (y[n] + sum_{e: dst=n} y[src_e]) + bias )
template <int D, int MODE>
__global__ __launch_bounds__(256) void agg_kernel(const __half* __restrict__ Yh,
                                                  const float* __restrict__ bias,
                                                  float* __restrict__ outp) {
    int gw = (blockIdx.x * 256 + threadIdx.x) >> 5;
    if (gw >= NN) return;
    int lane = threadIdx.x & 31;
    int beg = g_rowptr[gw], end = g_rowptr[gw + 1];
    float nm = g_norm[gw];
    if constexpr (D == 128) {
        const uint2* Y4 = (const uint2*)Yh;  // 4 halves per lane per row
        uint2 sv = Y4[(size_t)gw * 32 + lane];
        float2 f0 = u2f2(sv.x), f1 = u2f2(sv.y);
        float4 acc = make_float4(f0.x, f0.y, f1.x, f1.y);
        int sn = (beg < end) ? g_col[beg] : 0;
        for (int e = beg; e < end; e++) {
            int s = sn;
            if (e + 1 < end) sn = g_col[e + 1];
            uint2 v = Y4[(size_t)s * 32 + lane];
            float2 a = u2f2(v.x), b = u2f2(v.y);
            acc.x += a.x; acc.y += a.y; acc.z += b.x; acc.w += b.y;
        }
        float4 b = ((const float4*)bias)[lane];
        float4 o = make_float4(acc.x * nm + b.x, acc.y * nm + b.y,
                               acc.z * nm + b.z, acc.w * nm + b.w);
        float4* O4 = (float4*)outp;
        size_t idx = (size_t)gw * 32 + lane;
        if constexpr (MODE == 0) {
            O4[idx] = make_float4(lk(o.x), lk(o.y), lk(o.z), lk(o.w));
        } else if constexpr (MODE == 1) {
            float4 r = O4[idx];
            O4[idx] = make_float4((r.x + lk(o.x)) * 0.5f, (r.y + lk(o.y)) * 0.5f,
                                  (r.z + lk(o.z)) * 0.5f, (r.w + lk(o.w)) * 0.5f);
        } else {
            O4[idx] = o;
        }
    } else {  // D == 64
        const unsigned* Y2 = (const unsigned*)Yh;  // 2 halves per lane per row
        float2 acc = u2f2(Y2[(size_t)gw * 32 + lane]);
        int sn = (beg < end) ? g_col[beg] : 0;
        for (int e = beg; e < end; e++) {
            int s = sn;
            if (e + 1 < end) sn = g_col[e + 1];
            float2 v = u2f2(Y2[(size_t)s * 32 + lane]);
            acc.x += v.x; acc.y += v.y;
        }
        float2 b = ((const float2*)bias)[lane];
        float2 o = make_float2(acc.x * nm + b.x, acc.y * nm + b.y);
        float2* O2 = (float2*)outp;
        size_t idx = (size_t)gw * 32 + lane;
        if constexpr (MODE == 0) {
            O2[idx] = make_float2(lk(o.x), lk(o.y));
        } else if constexpr (MODE == 1) {
            float2 r = O2[idx];
            O2[idx] = make_float2((r.x + lk(o.x)) * 0.5f, (r.y + lk(o.y)) * 0.5f);
        } else {
            O2[idx] = o;
        }
    }
}

// ---------------- launch ----------------
extern "C" void kernel_launch(void* const* d_in, const int* in_sizes, int n_in,
                              void* d_out, int out_size) {
    const float* inputs = (const float*)d_in[0];
    const int*   edges  = (const int*)d_in[1];
    const float* w_in   = (const float*)d_in[2];
    const float* b_in   = (const float*)d_in[3];
    const float* w1     = (const float*)d_in[4];
    const float* b1     = (const float*)d_in[5];
    const float* w2     = (const float*)d_in[6];
    const float* b2     = (const float*)d_in[7];
    const float* w_out  = (const float*)d_in[8];
    const float* b_out  = (const float*)d_in[9];
    float* out = (float*)d_out;

    const int* src = edges;
    const int* dst = edges + NE;

    void *pyh, *pxv, *phv, *pwh, *pwl;
    cudaGetSymbolAddress(&pyh, g_yh);
    cudaGetSymbolAddress(&pxv, g_x);
    cudaGetSymbolAddress(&phv, g_h);
    cudaGetSymbolAddress(&pwh, g_wh);
    cudaGetSymbolAddress(&pwl, g_wl);
    __half* yh = (__half*)pyh;
    float* xv = (float*)pxv;
    float* hv = (float*)phv;
    __nv_bfloat16* wh = (__nv_bfloat16*)pwh;
    __nv_bfloat16* wl = (__nv_bfloat16*)pwl;

    const int GN = (NN + 255) / 256;
    const int GE = (NE + 255) / 256;
    const int GG = (NN + 127) / 128;       // gemm blocks
    const int GA = (NN * 32 + 255) / 256;  // agg blocks (warp/node)
    const int GW = (NMAT * HD * HD + 255) / 256;

    // weight split/transpose + CSR build
    prep_w_kernel<<<GW, 256>>>(w_in, w1, w2, w_out);
    zero_cnt_kernel<<<GN, 256>>>();
    count_kernel<<<GE, 256>>>(dst);
    scan_norm_kernel<<<1, 1024>>>();
    fill_kernel<<<GE, 256>>>(src, dst);

    // input conv
    gemm_tc_kernel<128><<<GG, 256>>>(inputs, wh, wl, yh);
    agg_kernel<128, 0><<<GA, 256>>>(yh, b_in, xv);

    // 6 residual blocks
    for (int i = 0; i < 6; i++) {
        gemm_tc_kernel<128><<<GG, 256>>>(xv, wh + (size_t)(1 + i) * HD * HD,
                                         wl + (size_t)(1 + i) * HD * HD, yh);
        agg_kernel<128, 0><<<GA, 256>>>(yh, b1 + (size_t)i * HD, hv);
        gemm_tc_kernel<128><<<GG, 256>>>(hv, wh + (size_t)(7 + i) * HD * HD,
                                         wl + (size_t)(7 + i) * HD * HD, yh);
        agg_kernel<128, 1><<<GA, 256>>>(yh, b2 + (size_t)i * HD, xv);
    }

    // output conv (no activation), writes first N*64 floats of d_out
    gemm_tc_kernel<64><<<GG, 256>>>(xv, wh + (size_t)13 * HD * HD,
                                    wl + (size_t)13 * HD * HD, yh);
    agg_kernel<64, 2><<<GA, 256>>>(yh, b_out, out);

    // second output: x (N*128) after the blocks
    cudaMemcpyAsync(out + (size_t)NN * 64, xv, (size_t)NN * HD * sizeof(float),
                    cudaMemcpyDeviceToDevice);
}

// round 5
// speedup vs baseline: 1.6016x; 1.0893x over previous
#include <cuda_runtime.h>
#include <cuda_fp16.h>
#include <cuda_bf16.h>

#define NN 50000
#define NE 800000
#define HD 128
#define NMAT 14
#define NSB 49   // scan blocks: ceil(50000/1024)

// ---------------- device scratch (no allocations allowed) ----------------
__device__ __half  g_yh[(size_t)NN * HD];   // fp16 messages (GEMM output, norm-scaled)
__device__ float   g_x[(size_t)NN * HD];    // running x (fp32)
__device__ float   g_h[(size_t)NN * HD];    // block intermediate h
__device__ float   g_norm[NN];
__device__ int     g_rowptr[NN + 1];
__device__ int     g_cnt[NN];
__device__ int     g_off[NN];
__device__ int     g_col[NE];
__device__ int     g_bsum[NSB];
__device__ __nv_bfloat16 g_wh[(size_t)NMAT * HD * HD];  // weights, n-major, hi part
__device__ __nv_bfloat16 g_wl[(size_t)NMAT * HD * HD];  // lo part

__device__ __forceinline__ float lk(float v) { return v >= 0.f ? v : 0.01f * v; }

__device__ __forceinline__ float2 u2f2(unsigned u) {
    __half2 h = *reinterpret_cast<__half2*>(&u);
    return __half22float2(h);
}

// ---------------- CSR build ----------------
__global__ void count_kernel(const int* __restrict__ dst) {
    int e = blockIdx.x * blockDim.x + threadIdx.x;
    if (e < NE) atomicAdd(&g_cnt[dst[e]], 1);
}

// phase 1: per-block exclusive scan of g_cnt -> g_rowptr (block-local), totals -> g_bsum
__global__ __launch_bounds__(1024) void scan_blocks_kernel() {
    __shared__ int ws[32];
    int tid = threadIdx.x, lane = tid & 31, wid = tid >> 5;
    int i = blockIdx.x * 1024 + tid;
    int v = (i < NN) ? g_cnt[i] : 0;
    int x = v;
#pragma unroll
    for (int d = 1; d < 32; d <<= 1) {
        int t = __shfl_up_sync(0xffffffffu, x, d);
        if (lane >= d) x += t;
    }
    if (lane == 31) ws[wid] = x;
    __syncthreads();
    if (wid == 0) {
        int s = ws[lane];
#pragma unroll
        for (int d = 1; d < 32; d <<= 1) {
            int t = __shfl_up_sync(0xffffffffu, s, d);
            if (lane >= d) s += t;
        }
        ws[lane] = s;
    }
    __syncthreads();
    int off = wid ? ws[wid - 1] : 0;
    if (i < NN) g_rowptr[i] = off + x - v;
    if (tid == 1023) g_bsum[blockIdx.x] = off + x;
}

// phase 2: one warp scans the NSB block totals (exclusive, in place)
__global__ void scan_tops_kernel() {
    int lane = threadIdx.x;
    int carry = 0;
    for (int base = 0; base < NSB; base += 32) {
        int i = base + lane;
        int v = (i < NSB) ? g_bsum[i] : 0;
        int x = v;
#pragma unroll
        for (int d = 1; d < 32; d <<= 1) {
            int t = __shfl_up_sync(0xffffffffu, x, d);
            if (lane >= d) x += t;
        }
        if (i < NSB) g_bsum[i] = carry + x - v;
        carry += __shfl_sync(0xffffffffu, x, 31);
    }
    if (lane == 0) g_rowptr[NN] = NE;
}

// phase 3: add block offsets, init g_off and norm
__global__ __launch_bounds__(1024) void scan_fix_kernel() {
    int i = blockIdx.x * 1024 + threadIdx.x;
    if (i < NN) {
        int r = g_rowptr[i] + g_bsum[blockIdx.x];
        g_rowptr[i] = r;
        g_off[i] = r;
        g_norm[i] = rsqrtf(1.0f + (float)g_cnt[i]);
    }
}

__global__ void fill_kernel(const int* __restrict__ src, const int* __restrict__ dst) {
    int e = blockIdx.x * blockDim.x + threadIdx.x;
    if (e < NE) {
        int d = dst[e];
        int p = atomicAdd(&g_off[d], 1);
        g_col[p] = src[e];
    }
}

// ---------------- weight prep: transpose to n-major, split fp32 -> bf16 hi/lo ----
__global__ void prep_w_kernel(const float* __restrict__ w_in, const float* __restrict__ w1,
                              const float* __restrict__ w2, const float* __restrict__ w_out) {
    int idx = blockIdx.x * blockDim.x + threadIdx.x;
    if (idx >= NMAT * HD * HD) return;
    int mat = idx >> 14;
    int rem = idx & 16383;
    int n = rem >> 7, k = rem & 127;
    float v;
    if (mat == 0)       v = w_in[k * HD + n];
    else if (mat <= 6)  v = w1[(size_t)(mat - 1) * HD * HD + k * HD + n];
    else if (mat <= 12) v = w2[(size_t)(mat - 7) * HD * HD + k * HD + n];
    else                v = (n < 64) ? w_out[k * 64 + n] : 0.f;
    __nv_bfloat16 hi = __float2bfloat16(v);
    __nv_bfloat16 lo = __float2bfloat16(v - __bfloat162float(hi));
    g_wh[idx] = hi;
    g_wl[idx] = lo;
}

// ---------------- bf16x2 split tensor-core GEMM ----------------
__device__ __forceinline__ void mma_bf16(float* c, unsigned a0, unsigned a1, unsigned a2,
                                         unsigned a3, unsigned b0, unsigned b1) {
    asm volatile(
        "mma.sync.aligned.m16n8k16.row.col.f32.bf16.bf16.f32 "
        "{%0,%1,%2,%3}, {%4,%5,%6,%7}, {%8,%9}, {%0,%1,%2,%3};"
        : "+f"(c[0]), "+f"(c[1]), "+f"(c[2]), "+f"(c[3])
        : "r"(a0), "r"(a1), "r"(a2), "r"(a3), "r"(b0), "r"(b1));
}

template <int BN>
__global__ __launch_bounds__(256) void gemm_tc_kernel(const float* __restrict__ A,
                                                      const __nv_bfloat16* __restrict__ Wh,
                                                      const __nv_bfloat16* __restrict__ Wl,
                                                      __half* __restrict__ Yh) {
    constexpr int BM = 128, BK = 32, K = 128;
    constexpr int WN = BN / 4;
    constexpr int NT = WN / 8;
    constexpr int SA = 40;
    __shared__ __nv_bfloat16 sAh[BM * SA], sAl[BM * SA];
    __shared__ __nv_bfloat16 sBh[BN * SA], sBl[BN * SA];

    const int tid = threadIdx.x, lane = tid & 31, wid = tid >> 5;
    const int g = lane >> 2, t = lane & 3;
    const int wm = (wid & 1) * 64, wn = (wid >> 1) * WN;
    const int m0 = blockIdx.x * BM;

    float acc[4][NT][4];
#pragma unroll
    for (int i = 0; i < 4; i++)
#pragma unroll
        for (int j = 0; j < NT; j++)
#pragma unroll
            for (int q = 0; q < 4; q++) acc[i][j][q] = 0.f;

    float4 va[4];
    uint4 vbh[2], vbl[2];

    auto loadA = [&](int k0) {
#pragma unroll
        for (int l = 0; l < 4; l++) {
            int idx = tid + l * 256, r = idx >> 3, c = idx & 7;
            va[l] = make_float4(0.f, 0.f, 0.f, 0.f);
            if (m0 + r < NN) va[l] = *(const float4*)(A + (size_t)(m0 + r) * K + k0 + c * 4);
        }
    };
    auto loadB = [&](int k0) {
        if constexpr (BN == 128) {
            int n = tid >> 1, kh = (tid & 1) * 16;
            vbh[0] = *(const uint4*)&Wh[(size_t)n * K + k0 + kh];
            vbh[1] = *(const uint4*)&Wh[(size_t)n * K + k0 + kh + 8];
            vbl[0] = *(const uint4*)&Wl[(size_t)n * K + k0 + kh];
            vbl[1] = *(const uint4*)&Wl[(size_t)n * K + k0 + kh + 8];
        } else {
            int n = tid >> 2, kh = (tid & 3) * 8;
            vbh[0] = *(const uint4*)&Wh[(size_t)n * K + k0 + kh];
            vbl[0] = *(const uint4*)&Wl[(size_t)n * K + k0 + kh];
        }
    };
    auto storeTiles = [&]() {
#pragma unroll
        for (int l = 0; l < 4; l++) {
            int idx = tid + l * 256, r = idx >> 3, c = idx & 7;
            float4 v = va[l];
            __nv_bfloat16 h0 = __float2bfloat16(v.x), h1 = __float2bfloat16(v.y);
            __nv_bfloat16 h2 = __float2bfloat16(v.z), h3 = __float2bfloat16(v.w);
            __nv_bfloat162 p01, p23, q01, q23;
            p01.x = h0; p01.y = h1; p23.x = h2; p23.y = h3;
            q01.x = __float2bfloat16(v.x - __bfloat162float(h0));
            q01.y = __float2bfloat16(v.y - __bfloat162float(h1));
            q23.x = __float2bfloat16(v.z - __bfloat162float(h2));
            q23.y = __float2bfloat16(v.w - __bfloat162float(h3));
            *(__nv_bfloat162*)&sAh[r * SA + c * 4]     = p01;
            *(__nv_bfloat162*)&sAh[r * SA + c * 4 + 2] = p23;
            *(__nv_bfloat162*)&sAl[r * SA + c * 4]     = q01;
            *(__nv_bfloat162*)&sAl[r * SA + c * 4 + 2] = q23;
        }
        if constexpr (BN == 128) {
            int n = tid >> 1, kh = (tid & 1) * 16;
            *(uint4*)&sBh[n * SA + kh]     = vbh[0];
            *(uint4*)&sBh[n * SA + kh + 8] = vbh[1];
            *(uint4*)&sBl[n * SA + kh]     = vbl[0];
            *(uint4*)&sBl[n * SA + kh + 8] = vbl[1];
        } else {
            int n = tid >> 2, kh = (tid & 3) * 8;
            *(uint4*)&sBh[n * SA + kh] = vbh[0];
            *(uint4*)&sBl[n * SA + kh] = vbl[0];
        }
    };

    loadA(0);
    loadB(0);
    for (int k0 = 0; k0 < K; k0 += BK) {
        storeTiles();
        __syncthreads();
        if (k0 + BK < K) { loadA(k0 + BK); loadB(k0 + BK); }
#pragma unroll
        for (int kk = 0; kk < BK; kk += 16) {
            unsigned bh[NT][2], bl[NT][2];
#pragma unroll
            for (int nt = 0; nt < NT; nt++) {
                int n = wn + nt * 8 + g;
                bh[nt][0] = *(const unsigned*)&sBh[n * SA + kk + 2 * t];
                bh[nt][1] = *(const unsigned*)&sBh[n * SA + kk + 2 * t + 8];
                bl[nt][0] = *(const unsigned*)&sBl[n * SA + kk + 2 * t];
                bl[nt][1] = *(const unsigned*)&sBl[n * SA + kk + 2 * t + 8];
            }
#pragma unroll
            for (int mt = 0; mt < 4; mt++) {
                int m = wm + mt * 16 + g;
                unsigned ah0 = *(const unsigned*)&sAh[m * SA + kk + 2 * t];
                unsigned ah1 = *(const unsigned*)&sAh[(m + 8) * SA + kk + 2 * t];
                unsigned ah2 = *(const unsigned*)&sAh[m * SA + kk + 2 * t + 8];
                unsigned ah3 = *(const unsigned*)&sAh[(m + 8) * SA + kk + 2 * t + 8];
                unsigned al0 = *(const unsigned*)&sAl[m * SA + kk + 2 * t];
                unsigned al1 = *(const unsigned*)&sAl[(m + 8) * SA + kk + 2 * t];
                unsigned al2 = *(const unsigned*)&sAl[m * SA + kk + 2 * t + 8];
                unsigned al3 = *(const unsigned*)&sAl[(m + 8) * SA + kk + 2 * t + 8];
#pragma unroll
                for (int nt = 0; nt < NT; nt++) {
                    mma_bf16(acc[mt][nt], ah0, ah1, ah2, ah3, bh[nt][0], bh[nt][1]);
                    mma_bf16(acc[mt][nt], ah0, ah1, ah2, ah3, bl[nt][0], bl[nt][1]);
                    mma_bf16(acc[mt][nt], al0, al1, al2, al3, bh[nt][0], bh[nt][1]);
                }
            }
        }
        __syncthreads();
    }

#pragma unroll
    for (int mt = 0; mt < 4; mt++) {
        int r0 = m0 + wm + mt * 16 + g, r1 = r0 + 8;
        float n0 = (r0 < NN) ? g_norm[r0] : 0.f;
        float n1 = (r1 < NN) ? g_norm[r1] : 0.f;
#pragma unroll
        for (int nt = 0; nt < NT; nt++) {
            int col = wn + nt * 8 + 2 * t;
            if (r0 < NN) {
                __half2 h = __floats2half2_rn(acc[mt][nt][0] * n0, acc[mt][nt][1] * n0);
                *(__half2*)(Yh + (size_t)r0 * BN + col) = h;
            }
            if (r1 < NN) {
                __half2 h = __floats2half2_rn(acc[mt][nt][2] * n1, acc[mt][nt][3] * n1);
                *(__half2*)(Yh + (size_t)r1 * BN + col) = h;
            }
        }
    }
}

// ---------------- Aggregation: one warp per node, fp16 gather, fp32 accum --------
// out[n] = f( norm[n] * (y[n] + sum_{e: dst=n} y[src_e]) + bias )
// MODE 0: leaky   MODE 1: residual (x+leaky)/2 in place   MODE 2: plain
// MODE 3: residual AND mirror write to out2 (fuses final x copy)
template <int D, int MODE>
__global__ __launch_bounds__(128) void agg_kernel(const __half* __restrict__ Yh,
                                                  const float* __restrict__ bias,
                                                  float* __restrict__ outp,
                                                  float* __restrict__ out2) {
    int gw = (blockIdx.x * 128 + threadIdx.x) >> 5;
    if (gw >= NN) return;
    int lane = threadIdx.x & 31;
    int beg = g_rowptr[gw], end = g_rowptr[gw + 1];
    float nm = g_norm[gw];
    const int* __restrict__ col = g_col;
    if constexpr (D == 128) {
        const uint2* Y4 = (const uint2*)Yh;
        uint2 sv = Y4[(size_t)gw * 32 + lane];
        float2 f0 = u2f2(sv.x), f1 = u2f2(sv.y);
        float4 acc = make_float4(f0.x, f0.y, f1.x, f1.y);
        int e = beg;
        for (; e + 3 < end; e += 4) {
            int s0 = col[e], s1 = col[e + 1], s2 = col[e + 2], s3 = col[e + 3];
            uint2 v0 = Y4[(size_t)s0 * 32 + lane];
            uint2 v1 = Y4[(size_t)s1 * 32 + lane];
            uint2 v2 = Y4[(size_t)s2 * 32 + lane];
            uint2 v3 = Y4[(size_t)s3 * 32 + lane];
            float2 a0 = u2f2(v0.x), b0 = u2f2(v0.y);
            float2 a1 = u2f2(v1.x), b1 = u2f2(v1.y);
            float2 a2 = u2f2(v2.x), b2 = u2f2(v2.y);
            float2 a3 = u2f2(v3.x), b3 = u2f2(v3.y);
            acc.x += (a0.x + a1.x) + (a2.x + a3.x);
            acc.y += (a0.y + a1.y) + (a2.y + a3.y);
            acc.z += (b0.x + b1.x) + (b2.x + b3.x);
            acc.w += (b0.y + b1.y) + (b2.y + b3.y);
        }
        for (; e < end; e++) {
            uint2 v = Y4[(size_t)col[e] * 32 + lane];
            float2 a = u2f2(v.x), b = u2f2(v.y);
            acc.x += a.x; acc.y += a.y; acc.z += b.x; acc.w += b.y;
        }
        float4 b = ((const float4*)bias)[lane];
        float4 o = make_float4(acc.x * nm + b.x, acc.y * nm + b.y,
                               acc.z * nm + b.z, acc.w * nm + b.w);
        float4* O4 = (float4*)outp;
        size_t idx = (size_t)gw * 32 + lane;
        if constexpr (MODE == 0) {
            O4[idx] = make_float4(lk(o.x), lk(o.y), lk(o.z), lk(o.w));
        } else if constexpr (MODE == 1 || MODE == 3) {
            float4 r = O4[idx];
            float4 nv = make_float4((r.x + lk(o.x)) * 0.5f, (r.y + lk(o.y)) * 0.5f,
                                    (r.z + lk(o.z)) * 0.5f, (r.w + lk(o.w)) * 0.5f);
            O4[idx] = nv;
            if constexpr (MODE == 3) ((float4*)out2)[idx] = nv;
        } else {
            O4[idx] = o;
        }
    } else {  // D == 64
        const unsigned* Y2 = (const unsigned*)Yh;
        float2 acc = u2f2(Y2[(size_t)gw * 32 + lane]);
        int e = beg;
        for (; e + 3 < end; e += 4) {
            int s0 = col[e], s1 = col[e + 1], s2 = col[e + 2], s3 = col[e + 3];
            float2 v0 = u2f2(Y2[(size_t)s0 * 32 + lane]);
            float2 v1 = u2f2(Y2[(size_t)s1 * 32 + lane]);
            float2 v2 = u2f2(Y2[(size_t)s2 * 32 + lane]);
            float2 v3 = u2f2(Y2[(size_t)s3 * 32 + lane]);
            acc.x += (v0.x + v1.x) + (v2.x + v3.x);
            acc.y += (v0.y + v1.y) + (v2.y + v3.y);
        }
        for (; e < end; e++) {
            float2 v = u2f2(Y2[(size_t)col[e] * 32 + lane]);
            acc.x += v.x; acc.y += v.y;
        }
        float2 b = ((const float2*)bias)[lane];
        float2 o = make_float2(acc.x * nm + b.x, acc.y * nm + b.y);
        float2* O2 = (float2*)outp;
        size_t idx = (size_t)gw * 32 + lane;
        if constexpr (MODE == 0) {
            O2[idx] = make_float2(lk(o.x), lk(o.y));
        } else if constexpr (MODE == 1 || MODE == 3) {
            float2 r = O2[idx];
            float2 nv = make_float2((r.x + lk(o.x)) * 0.5f, (r.y + lk(o.y)) * 0.5f);
            O2[idx] = nv;
            if constexpr (MODE == 3) ((float2*)out2)[idx] = nv;
        } else {
            O2[idx] = o;
        }
    }
}

// ---------------- launch ----------------
extern "C" void kernel_launch(void* const* d_in, const int* in_sizes, int n_in,
                              void* d_out, int out_size) {
    const float* inputs = (const float*)d_in[0];
    const int*   edges  = (const int*)d_in[1];
    const float* w_in   = (const float*)d_in[2];
    const float* b_in   = (const float*)d_in[3];
    const float* w1     = (const float*)d_in[4];
    const float* b1     = (const float*)d_in[5];
    const float* w2     = (const float*)d_in[6];
    const float* b2     = (const float*)d_in[7];
    const float* w_out  = (const float*)d_in[8];
    const float* b_out  = (const float*)d_in[9];
    float* out = (float*)d_out;

    const int* src = edges;
    const int* dst = edges + NE;

    void *pyh, *pxv, *phv, *pwh, *pwl, *pcnt;
    cudaGetSymbolAddress(&pyh, g_yh);
    cudaGetSymbolAddress(&pxv, g_x);
    cudaGetSymbolAddress(&phv, g_h);
    cudaGetSymbolAddress(&pwh, g_wh);
    cudaGetSymbolAddress(&pwl, g_wl);
    cudaGetSymbolAddress(&pcnt, g_cnt);
    __half* yh = (__half*)pyh;
    float* xv = (float*)pxv;
    float* hv = (float*)phv;
    __nv_bfloat16* wh = (__nv_bfloat16*)pwh;
    __nv_bfloat16* wl = (__nv_bfloat16*)pwl;

    const int GE = (NE + 255) / 256;
    const int GG = (NN + 127) / 128;       // gemm blocks
    const int GA = (NN * 32 + 127) / 128;  // agg blocks (warp/node, 128-thr blocks)
    const int GW = (NMAT * HD * HD + 255) / 256;

    // weight split/transpose + CSR build
    prep_w_kernel<<<GW, 256>>>(w_in, w1, w2, w_out);
    cudaMemsetAsync(pcnt, 0, NN * sizeof(int));
    count_kernel<<<GE, 256>>>(dst);
    scan_blocks_kernel<<<NSB, 1024>>>();
    scan_tops_kernel<<<1, 32>>>();
    scan_fix_kernel<<<NSB, 1024>>>();
    fill_kernel<<<GE, 256>>>(src, dst);

    // input conv
    gemm_tc_kernel<128><<<GG, 256>>>(inputs, wh, wl, yh);
    agg_kernel<128, 0><<<GA, 128>>>(yh, b_in, xv, nullptr);

    // 6 residual blocks; last one mirrors x into d_out's second half
    for (int i = 0; i < 6; i++) {
        gemm_tc_kernel<128><<<GG, 256>>>(xv, wh + (size_t)(1 + i) * HD * HD,
                                         wl + (size_t)(1 + i) * HD * HD, yh);
        agg_kernel<128, 0><<<GA, 128>>>(yh, b1 + (size_t)i * HD, hv, nullptr);
        gemm_tc_kernel<128><<<GG, 256>>>(hv, wh + (size_t)(7 + i) * HD * HD,
                                         wl + (size_t)(7 + i) * HD * HD, yh);
        if (i < 5)
            agg_kernel<128, 1><<<GA, 128>>>(yh, b2 + (size_t)i * HD, xv, nullptr);
        else
            agg_kernel<128, 3><<<GA, 128>>>(yh, b2 + (size_t)i * HD, xv,
                                            out + (size_t)NN * 64);
    }

    // output conv (no activation), writes first N*64 floats of d_out
    gemm_tc_kernel<64><<<GG, 256>>>(xv, wh + (size_t)13 * HD * HD,
                                    wl + (size_t)13 * HD * HD, yh);
    agg_kernel<64, 2><<<GA, 128>>>(yh, b_out, out, nullptr);
}